// round 2
// baseline (speedup 1.0000x reference)
#include <cuda_runtime.h>

#define NGATE   16000
#define NG      8000
#define NCTA    128
#define GPC     125      // gates per CTA: 128*125 = 16000
#define NB      32
#define NP      64
#define NITER   50
#define DTF     0.02f
#define INV_DT_SKIP 2.5f

typedef unsigned long long u64;

// ---------------- device scratch (no allocations allowed) ----------------
__device__ float    g_ab[2][NB*NP];
__device__ float    g_a0[NB*NP];
__device__ float    g_f[NB*NP];
__device__ float    g_S[NB*NP];
__device__ float    g_inv[2][NP*NP];
__device__ unsigned g_counter;
__device__ unsigned g_epoch;

// ---------------- packed f32x2 + memory-order helpers ----------------
__device__ __forceinline__ u64 fma2(u64 a, u64 b, u64 c) {
    u64 d; asm("fma.rn.f32x2 %0, %1, %2, %3;" : "=l"(d) : "l"(a), "l"(b), "l"(c)); return d;
}
__device__ __forceinline__ u64 mul2(u64 a, u64 b) {
    u64 d; asm("mul.rn.f32x2 %0, %1, %2;" : "=l"(d) : "l"(a), "l"(b)); return d;
}
__device__ __forceinline__ u64 dup2(float x) {
    unsigned xi = __float_as_uint(x);
    u64 d; asm("mov.b64 %0, {%1, %2};" : "=l"(d) : "r"(xi), "r"(xi)); return d;
}
__device__ __forceinline__ void unpack2(u64 v, float& lo, float& hi) {
    unsigned a, b; asm("mov.b64 {%0, %1}, %2;" : "=r"(a), "=r"(b) : "l"(v));
    lo = __uint_as_float(a); hi = __uint_as_float(b);
}
__device__ __forceinline__ unsigned ldacq(const unsigned* p) {
    unsigned v; asm volatile("ld.acquire.gpu.u32 %0, [%1];" : "=r"(v) : "l"(p)); return v;
}
__device__ __forceinline__ void strel(unsigned* p, unsigned v) {
    asm volatile("st.release.gpu.u32 [%0], %1;" :: "l"(p), "r"(v));
}
__device__ __forceinline__ unsigned atom_inc_acqrel(unsigned* p) {
    unsigned v, one = 1u;
    asm volatile("atom.add.acq_rel.gpu.u32 %0, [%1], %2;" : "=r"(v) : "l"(p), "r"(one)); return v;
}
__device__ __forceinline__ void redadd(float* p, float v) {
    asm volatile("red.add.f32 [%0], %1;" :: "l"(p), "f"(v));
}
__device__ __forceinline__ float f4c(const float4 v, int j) {
    switch (j) { case 0: return v.x; case 1: return v.y; case 2: return v.z; default: return v.w; }
}

// ---------------- init: matrix inverses + state copy + reset ----------------
__global__ void init_kernel(const float* __restrict__ state, const float* __restrict__ Ap) {
    __shared__ float M[NP][2*NP + 1];
    __shared__ float fac[NP];
    __shared__ float s_piv;
    int t = threadIdx.x;

    for (int pass = 0; pass < 2; ++pass) {
        float dscale = (pass == 0) ? 1.0f : 3.0f;
        float ascale = (pass == 0) ? DTF : 2.0f * DTF;
        for (int idx = t; idx < NP*NP; idx += 256) {
            int i = idx >> 6, j = idx & 63;
            M[i][j]      = ((i == j) ? dscale : 0.0f) - ascale * Ap[idx];
            M[i][j + NP] = (i == j) ? 1.0f : 0.0f;
        }
        __syncthreads();
        for (int c = 0; c < NP; ++c) {
            if (t == 0) s_piv = 1.0f / M[c][c];
            __syncthreads();
            float ip = s_piv;
            if (t < 2*NP) M[c][t] *= ip;
            if (t < NP)   fac[t] = (t == c) ? 0.0f : M[t][c];
            __syncthreads();
            for (int idx = t; idx < NP * 2 * NP; idx += 256) {
                int r = idx >> 7, j = idx & 127;
                if (r != c) M[r][j] -= fac[r] * M[c][j];
            }
            __syncthreads();
        }
        for (int idx = t; idx < NP*NP; idx += 256) {
            int i = idx >> 6, j = idx & 63;
            g_inv[pass][idx] = M[i][j + NP];
        }
        __syncthreads();
    }
    for (int idx = t; idx < NB*NP; idx += 256) {
        float v = state[idx];
        g_ab[0][idx] = v; g_a0[idx] = v; g_S[idx] = 0.0f; g_f[idx] = 0.0f;
    }
    if (t == 0) { g_counter = 0u; strel(&g_epoch, 0u); }
}

// ---------------- persistent time-stepping kernel ----------------
#define SM_INV  0
#define SM_PP   65536
#define SM_F    (65536 + 64000)
#define SM_A    (65536 + 64000 + 16000)
#define SMEM_TOTAL (65536 + 64000 + 16000 + 8192)

extern __shared__ char smem_raw[];

__global__ void __launch_bounds__(256, 1)
persist_kernel(const float* __restrict__ Wu, const float* __restrict__ Wv,
               const float* __restrict__ Pp, float* __restrict__ out)
{
    u64* inv_sm = (u64*)(smem_raw + SM_INV);  // [2][64 j][64 i] dup'd
    u64* pp_sm  = (u64*)(smem_raw + SM_PP);   // [125 gl][64 p]  dup'd
    u64* f_sm   = (u64*)(smem_raw + SM_F);    // [125 gl][16 bp]
    u64* a_sm   = (u64*)(smem_raw + SM_A);    // [64 k][16 bp]
    u64* r_sm   = f_sm;                       // updater overlay
    __shared__ int s_upd;

    const int t   = threadIdx.x;
    const int cta = blockIdx.x;

    // stage inv (j-major, dup'd) and this CTA's P_proj chunk (dup'd)
    for (int idx = t; idx < 2*NP*NP; idx += 256) {
        int m = idx >> 12, j = (idx >> 6) & 63, i = idx & 63;
        inv_sm[idx] = dup2(g_inv[m][i*NP + j]);
    }
    for (int idx = t; idx < GPC*NP; idx += 256) {
        int gl = idx >> 6, p = idx & 63;
        pp_sm[idx] = dup2(Pp[p*NGATE + cta*GPC + gl]);
    }

    // phase-1 static mapping: thread = (local gate, batch half)
    const int gl = t >> 1, h = t & 1;
    const bool valid = (gl < GPC);
    int gate = cta * GPC + ((gl < GPC) ? gl : 0);
    const float4* W4 = (const float4*)((gate < NG) ? Wu : Wv);
    const int base = (gate < NG) ? gate : (gate - NG);
    const int r0 = (base         ) * 16;
    const int r1 = (base +     NG) * 16;
    const int r2 = (base + 2 * NG) * 16;
    const int r3 = (base + 3 * NG) * 16;
    // phase-2 static mapping: thread = (batch pair, p quad)
    const int bb = t & 15, pq = t >> 4;

    __syncthreads();

    for (int it = 0; it < NITER; ++it) {
        // ---- wait for epoch (a_{it} ready) ----
        if (t == 0) {
            while (ldacq(&g_epoch) < (unsigned)it) __nanosleep(32);
        }
        __syncthreads();

        // ---- stage a (transposed, batch-paired) ----
        const float* curA = g_ab[it & 1];
        for (int idx = t; idx < NB*NP; idx += 256) {
            int b = idx >> 6, k = idx & 63;
            float v = __ldcv(curA + idx);
            ((float*)(a_sm + k*16 + (b >> 1)))[b & 1] = v;
        }
        __syncthreads();

        // ---- phase 1: z = a @ W^T (4 comps), f = uu*dx + vv*dy ----
        if (valid) {
            u64 ac0[8], ac1[8], ac2[8], ac3[8];
            #pragma unroll
            for (int i = 0; i < 8; ++i) { ac0[i]=0; ac1[i]=0; ac2[i]=0; ac3[i]=0; }

            #pragma unroll 1
            for (int kb = 0; kb < 16; ++kb) {
                float4 w0 = __ldg(W4 + r0 + kb);
                float4 w1 = __ldg(W4 + r1 + kb);
                float4 w2 = __ldg(W4 + r2 + kb);
                float4 w3 = __ldg(W4 + r3 + kb);
                #pragma unroll
                for (int j = 0; j < 4; ++j) {
                    const ulonglong2* ar2 = (const ulonglong2*)(a_sm + (kb*4 + j)*16 + h*8);
                    ulonglong2 p0 = ar2[0], p1 = ar2[1], p2 = ar2[2], p3 = ar2[3];
                    u64 av[8] = {p0.x, p0.y, p1.x, p1.y, p2.x, p2.y, p3.x, p3.y};
                    u64 d0 = dup2(f4c(w0, j)), d1 = dup2(f4c(w1, j));
                    u64 d2 = dup2(f4c(w2, j)), d3 = dup2(f4c(w3, j));
                    #pragma unroll
                    for (int i = 0; i < 8; ++i) {
                        ac0[i] = fma2(d0, av[i], ac0[i]);
                        ac1[i] = fma2(d1, av[i], ac1[i]);
                        ac2[i] = fma2(d2, av[i], ac2[i]);
                        ac3[i] = fma2(d3, av[i], ac3[i]);
                    }
                }
            }
            #pragma unroll
            for (int i = 0; i < 8; ++i)
                f_sm[gl*16 + h*8 + i] = fma2(ac1[i], ac3[i], mul2(ac0[i], ac2[i]));
        }
        __syncthreads();

        // ---- phase 2: partial S[b][p] += sum_g f[b][g] * Pp[p][g] ----
        {
            u64 acc0 = 0, acc1 = 0, acc2 = 0, acc3 = 0;
            const u64* ffp = f_sm + bb;
            const u64* ppp = pp_sm + pq*4;
            #pragma unroll 4
            for (int g = 0; g < GPC; ++g) {
                u64 fv = ffp[g*16];
                const ulonglong2* pv2 = (const ulonglong2*)(ppp + g*64);
                ulonglong2 q0 = pv2[0], q1 = pv2[1];
                acc0 = fma2(fv, q0.x, acc0);
                acc1 = fma2(fv, q0.y, acc1);
                acc2 = fma2(fv, q1.x, acc2);
                acc3 = fma2(fv, q1.y, acc3);
            }
            u64 accs[4] = {acc0, acc1, acc2, acc3};
            #pragma unroll
            for (int q = 0; q < 4; ++q) {
                float lo, hi; unpack2(accs[q], lo, hi);
                redadd(g_S + (2*bb    )*NP + pq*4 + q, lo);
                redadd(g_S + (2*bb + 1)*NP + pq*4 + q, hi);
            }
        }

        // ---- arrive; elect last CTA as updater ----
        __threadfence();
        __syncthreads();
        if (t == 0) {
            unsigned old = atom_inc_acqrel(&g_counter);
            s_upd = (old == (unsigned)(NCTA*(it+1)) - 1u) ? 1 : 0;
        }
        __syncthreads();

        if (s_upd) {
            const int cur = it & 1, nxt = cur ^ 1;
            const float* acur  = g_ab[cur];
            float*       anext = g_ab[nxt];
            // f = -S ; r ; stage r batch-paired j-major ; reset S ; save f
            #pragma unroll
            for (int e = 0; e < 8; ++e) {
                int idx = t + e*256;
                int b = idx >> 6, j = idx & 63;
                float f = -__ldcv(g_S + idx);
                float av = __ldcv(acur + idx);
                float r;
                if (it == 0) {
                    r = av + DTF * f;
                } else {
                    float ap = __ldcv(anext + idx);   // a_{it-1} (about to be overwritten)
                    float fp = __ldcv(g_f + idx);
                    r = 4.0f*av - ap + 4.0f*DTF*f - 2.0f*DTF*fp;
                }
                __stcg(g_f + idx, f);
                __stcg(g_S + idx, 0.0f);
                ((float*)(r_sm + j*16 + (b >> 1)))[b & 1] = r;
            }
            __syncthreads();
            // a_next = inv @ r   (batch-paired matvec)
            const int bp = t & 15, iq = t >> 4;
            const u64* invm = inv_sm + ((it == 0) ? 0 : NP*NP) + iq*4;
            u64 a4[4] = {0, 0, 0, 0};
            #pragma unroll 4
            for (int j = 0; j < NP; ++j) {
                u64 rv = r_sm[j*16 + bp];
                const ulonglong2* iv2 = (const ulonglong2*)(invm + j*64);
                ulonglong2 q0 = iv2[0], q1 = iv2[1];
                a4[0] = fma2(rv, q0.x, a4[0]);
                a4[1] = fma2(rv, q0.y, a4[1]);
                a4[2] = fma2(rv, q1.x, a4[2]);
                a4[3] = fma2(rv, q1.y, a4[3]);
            }
            #pragma unroll
            for (int q = 0; q < 4; ++q) {
                int i = iq*4 + q;
                float lo, hi; unpack2(a4[q], lo, hi);
                if (it < NITER - 1) {
                    __stcg(anext + (2*bp    )*NP + i, lo);
                    __stcg(anext + (2*bp + 1)*NP + i, hi);
                } else {
                    out[(2*bp    )*NP + i] = (lo - g_a0[(2*bp    )*NP + i]) * INV_DT_SKIP;
                    out[(2*bp + 1)*NP + i] = (hi - g_a0[(2*bp + 1)*NP + i]) * INV_DT_SKIP;
                }
            }
            __threadfence();
            __syncthreads();
            if (t == 0) strel(&g_epoch, (unsigned)(it + 1));
        } else if (it == NITER - 1) {
            return;  // non-updaters are done; updater finishes the output
        }
    }
}

// ---------------- launcher ----------------
extern "C" void kernel_launch(void* const* d_in, const int* in_sizes, int n_in,
                              void* d_out, int out_size) {
    const float* state = (const float*)d_in[0];
    const float* Ap    = (const float*)d_in[1];
    const float* Wu    = (const float*)d_in[2];
    const float* Wv    = (const float*)d_in[3];
    const float* Pp    = (const float*)d_in[4];
    float* out = (float*)d_out;
    (void)in_sizes; (void)n_in; (void)out_size;

    cudaFuncSetAttribute(persist_kernel,
                         cudaFuncAttributeMaxDynamicSharedMemorySize, SMEM_TOTAL);

    init_kernel<<<1, 256>>>(state, Ap);
    persist_kernel<<<NCTA, 256, SMEM_TOTAL>>>(Wu, Wv, Pp, out);
}

// round 4
// speedup vs baseline: 1.0655x; 1.0655x over previous
#include <cuda_runtime.h>

#define NGATE   16000
#define NG      8000
#define NCTA    128
#define GPC     125      // gates per CTA: 128*125 = 16000
#define NB      32
#define NP      64
#define NITER   50
#define NT      512
#define DTF     0.02f
#define INV_DT_SKIP 2.5f

typedef unsigned long long u64;

// ---------------- device scratch ----------------
__device__ float    g_S[2][NB*NP];
__device__ float    g_inv[2][NP*NP];
__device__ unsigned g_counter;

// ---------------- packed f32x2 + memory-order helpers ----------------
__device__ __forceinline__ u64 fma2(u64 a, u64 b, u64 c) {
    u64 d; asm("fma.rn.f32x2 %0, %1, %2, %3;" : "=l"(d) : "l"(a), "l"(b), "l"(c)); return d;
}
__device__ __forceinline__ u64 mul2(u64 a, u64 b) {
    u64 d; asm("mul.rn.f32x2 %0, %1, %2;" : "=l"(d) : "l"(a), "l"(b)); return d;
}
__device__ __forceinline__ u64 dup2(float x) {
    unsigned xi = __float_as_uint(x);
    u64 d; asm("mov.b64 %0, {%1, %2};" : "=l"(d) : "r"(xi), "r"(xi)); return d;
}
__device__ __forceinline__ void unpack2(u64 v, float& lo, float& hi) {
    unsigned a, b; asm("mov.b64 {%0, %1}, %2;" : "=r"(a), "=r"(b) : "l"(v));
    lo = __uint_as_float(a); hi = __uint_as_float(b);
}
__device__ __forceinline__ unsigned ldacq(const unsigned* p) {
    unsigned v; asm volatile("ld.acquire.gpu.u32 %0, [%1];" : "=r"(v) : "l"(p)); return v;
}
__device__ __forceinline__ unsigned atom_inc_acqrel(unsigned* p) {
    unsigned v, one = 1u;
    asm volatile("atom.add.acq_rel.gpu.u32 %0, [%1], %2;" : "=r"(v) : "l"(p), "r"(one)); return v;
}
__device__ __forceinline__ void redadd(float* p, float v) {
    asm volatile("red.add.f32 [%0], %1;" :: "l"(p), "f"(v));
}
__device__ __forceinline__ float f4c(const float4 v, int j) {
    switch (j) { case 0: return v.x; case 1: return v.y; case 2: return v.z; default: return v.w; }
}

// ---------------- init: matrix inverses + reset ----------------
__global__ void init_kernel(const float* __restrict__ Ap) {
    __shared__ float M[NP][2*NP + 1];
    __shared__ float fac[NP];
    __shared__ float s_piv;
    int t = threadIdx.x;

    for (int pass = 0; pass < 2; ++pass) {
        float dscale = (pass == 0) ? 1.0f : 3.0f;
        float ascale = (pass == 0) ? DTF : 2.0f * DTF;
        for (int idx = t; idx < NP*NP; idx += 256) {
            int i = idx >> 6, j = idx & 63;
            M[i][j]      = ((i == j) ? dscale : 0.0f) - ascale * Ap[idx];
            M[i][j + NP] = (i == j) ? 1.0f : 0.0f;
        }
        __syncthreads();
        for (int c = 0; c < NP; ++c) {
            if (t == 0) s_piv = 1.0f / M[c][c];
            __syncthreads();
            float ip = s_piv;
            if (t < 2*NP) M[c][t] *= ip;
            if (t < NP)   fac[t] = (t == c) ? 0.0f : M[t][c];
            __syncthreads();
            for (int idx = t; idx < NP * 2 * NP; idx += 256) {
                int r = idx >> 7, j = idx & 127;
                if (r != c) M[r][j] -= fac[r] * M[c][j];
            }
            __syncthreads();
        }
        for (int idx = t; idx < NP*NP; idx += 256) {
            int i = idx >> 6, j = idx & 63;
            g_inv[pass][idx] = M[i][j + NP];
        }
        __syncthreads();
    }
    for (int idx = t; idx < 2*NB*NP; idx += 256) ((float*)g_S)[idx] = 0.0f;
    if (t == 0) g_counter = 0u;
    __threadfence();
}

// ---------------- persistent time-stepping kernel ----------------
// SMEM layout (bytes)
#define SM_INV   0                          // [2][64 j][64 i] dup'd u64 : 65536
#define SM_PP    65536                      // [125 gl][64 p]  dup'd u64 : 64000
#define SM_F     (SM_PP + 64000)            // [125 gl][16 bp] u64       : 16000
#define SM_A     (SM_F + 16000)             // [64 k][16 bp] u64 (a^T)   : 8192
#define SM_R     (SM_A + 8192)              // [64 j][16 bp] u64 (r^T)   : 8192
#define SM_ACUR  (SM_R + 8192)              // [2048] float (a, b-major) : 8192
#define SM_APRV  (SM_ACUR + 8192)           // [2048] float              : 8192
#define SM_FPRV  (SM_APRV + 8192)           // [2048] float              : 8192
#define SM_A0    (SM_FPRV + 8192)           // [2048] float              : 8192
#define SMEM_TOTAL (SM_A0 + 8192)

extern __shared__ char smem_raw[];

__global__ void __launch_bounds__(NT, 1)
persist_kernel(const float* __restrict__ state,
               const float* __restrict__ Wu, const float* __restrict__ Wv,
               const float* __restrict__ Pp, float* __restrict__ out)
{
    u64*   inv_sm = (u64*)(smem_raw + SM_INV);
    u64*   pp_sm  = (u64*)(smem_raw + SM_PP);
    u64*   f_sm   = (u64*)(smem_raw + SM_F);
    u64*   a_sm   = (u64*)(smem_raw + SM_A);
    u64*   r_sm   = (u64*)(smem_raw + SM_R);
    float* a_cur  = (float*)(smem_raw + SM_ACUR);
    float* a_prv  = (float*)(smem_raw + SM_APRV);
    float* f_prv  = (float*)(smem_raw + SM_FPRV);
    float* a0_sm  = (float*)(smem_raw + SM_A0);

    const int t   = threadIdx.x;
    const int cta = blockIdx.x;

    // ---- one-time staging ----
    for (int idx = t; idx < 2*NP*NP; idx += NT) {
        int m = idx >> 12, j = (idx >> 6) & 63, i = idx & 63;
        inv_sm[idx] = dup2(g_inv[m][i*NP + j]);
    }
    for (int idx = t; idx < GPC*NP; idx += NT) {
        int gl = idx >> 6, p = idx & 63;
        pp_sm[idx] = dup2(Pp[p*NGATE + cta*GPC + gl]);
    }
    for (int idx = t; idx < NB*NP; idx += NT) {
        float v = state[idx];
        int b = idx >> 6, k = idx & 63;
        a_cur[idx] = v; a0_sm[idx] = v;
        ((float*)(a_sm + k*16 + (b >> 1)))[b & 1] = v;
    }

    // phase-1 mapping: thread = (local gate gl, batch quarter q)
    const int gl = t >> 2, q = t & 3;
    const bool valid = (gl < GPC);
    const int gate = cta * GPC + (valid ? gl : 0);
    const float4* W4 = (const float4*)((gate < NG) ? Wu : Wv);
    const int base = (gate < NG) ? gate : (gate - NG);
    const int r0 = (base         ) * 16;
    const int r1 = (base +     NG) * 16;
    const int r2 = (base + 2 * NG) * 16;
    const int r3 = (base + 3 * NG) * 16;
    // phase-2 mapping: thread = (batch pair bb, p-pair p2)
    const int bb = t & 15, p2 = t >> 4;
    // update mapping: thread = (batch pair bp, i-pair i2)
    const int bp = t & 15, i2 = t >> 4;

    __syncthreads();

    for (int it = 0; it < NITER; ++it) {
        // ---------- phase 1: z = a @ W^T (4 comps), f = u*dx + v*dy ----------
        u64 ac0[4], ac1[4], ac2[4], ac3[4];
        #pragma unroll
        for (int i = 0; i < 4; ++i) { ac0[i]=0; ac1[i]=0; ac2[i]=0; ac3[i]=0; }

        float4 w0 = __ldg(W4 + r0), w1 = __ldg(W4 + r1);
        float4 w2 = __ldg(W4 + r2), w3 = __ldg(W4 + r3);
        #pragma unroll 1
        for (int kb = 0; kb < 16; ++kb) {
            float4 n0, n1, n2, n3;
            if (kb < 15) {
                n0 = __ldg(W4 + r0 + kb + 1); n1 = __ldg(W4 + r1 + kb + 1);
                n2 = __ldg(W4 + r2 + kb + 1); n3 = __ldg(W4 + r3 + kb + 1);
            }
            #pragma unroll
            for (int j = 0; j < 4; ++j) {
                const ulonglong2* ar2 = (const ulonglong2*)(a_sm + (kb*4 + j)*16 + q*4);
                ulonglong2 p0 = ar2[0], p1 = ar2[1];
                u64 av[4] = {p0.x, p0.y, p1.x, p1.y};
                u64 d0 = dup2(f4c(w0, j)), d1 = dup2(f4c(w1, j));
                u64 d2 = dup2(f4c(w2, j)), d3 = dup2(f4c(w3, j));
                #pragma unroll
                for (int i = 0; i < 4; ++i) {
                    ac0[i] = fma2(d0, av[i], ac0[i]);
                    ac1[i] = fma2(d1, av[i], ac1[i]);
                    ac2[i] = fma2(d2, av[i], ac2[i]);
                    ac3[i] = fma2(d3, av[i], ac3[i]);
                }
            }
            if (kb < 15) { w0 = n0; w1 = n1; w2 = n2; w3 = n3; }
        }
        if (valid) {
            #pragma unroll
            for (int i = 0; i < 4; ++i)
                f_sm[gl*16 + q*4 + i] = fma2(ac1[i], ac3[i], mul2(ac0[i], ac2[i]));
        }
        __syncthreads();

        // ---------- phase 2: partial S[b][p] += sum_g f[b][g]*Pp[p][g] ----------
        {
            float* Sb = g_S[it & 1];
            u64 acc0 = 0, acc1 = 0;
            const u64* ffp = f_sm + bb;
            const u64* ppp = pp_sm + p2*2;
            #pragma unroll 5
            for (int g = 0; g < GPC; ++g) {
                u64 fv = ffp[g*16];
                ulonglong2 pv = *(const ulonglong2*)(ppp + g*64);
                acc0 = fma2(fv, pv.x, acc0);
                acc1 = fma2(fv, pv.y, acc1);
            }
            float l0, h0, l1, h1;
            unpack2(acc0, l0, h0); unpack2(acc1, l1, h1);
            redadd(Sb + (2*bb    )*NP + p2*2    , l0);
            redadd(Sb + (2*bb + 1)*NP + p2*2    , h0);
            redadd(Sb + (2*bb    )*NP + p2*2 + 1, l1);
            redadd(Sb + (2*bb + 1)*NP + p2*2 + 1, h1);
        }

        // ---------- barrier 1: all partial sums visible ----------
        __threadfence();
        __syncthreads();
        if (t == 0) atom_inc_acqrel(&g_counter);
        const unsigned tgt1 = (unsigned)NCTA * (unsigned)(2*it + 1);
        if (it == NITER - 1 && cta != 0) return;   // arrived; only CTA0 finishes
        if (t == 0) { while (ldacq(&g_counter) < tgt1) __nanosleep(32); }
        __syncthreads();

        // ---------- update (every CTA, redundantly, into its own SMEM) ----------
        {
            const float* Sb = g_S[it & 1];
            #pragma unroll
            for (int e = 0; e < 4; ++e) {
                int idx = t + e*NT;
                int b = idx >> 6, j = idx & 63;
                float f  = -__ldcv(Sb + idx);
                float av = a_cur[idx];
                float r;
                if (it == 0) r = av + DTF * f;
                else {
                    float ap = a_prv[idx];
                    float fp = f_prv[idx];
                    r = 4.0f*av - ap + 4.0f*DTF*f - 2.0f*DTF*fp;
                }
                f_prv[idx] = f;
                a_prv[idx] = av;
                ((float*)(r_sm + j*16 + (b >> 1)))[b & 1] = r;
            }
            __syncthreads();
            // a_next = inv @ r
            const u64* invm = inv_sm + ((it == 0) ? 0 : NP*NP);
            u64 acc0 = 0, acc1 = 0;
            #pragma unroll 4
            for (int j = 0; j < NP; ++j) {
                u64 rv = r_sm[j*16 + bp];
                ulonglong2 iv = *(const ulonglong2*)(invm + j*64 + i2*2);
                acc0 = fma2(rv, iv.x, acc0);
                acc1 = fma2(rv, iv.y, acc1);
            }
            int i = i2*2;
            float l0, h0, l1, h1;
            unpack2(acc0, l0, h0); unpack2(acc1, l1, h1);
            if (it < NITER - 1) {
                a_sm[(i    )*16 + bp] = acc0;
                a_sm[(i + 1)*16 + bp] = acc1;
                a_cur[(2*bp    )*NP + i    ] = l0;
                a_cur[(2*bp + 1)*NP + i    ] = h0;
                a_cur[(2*bp    )*NP + i + 1] = l1;
                a_cur[(2*bp + 1)*NP + i + 1] = h1;
            } else { // cta 0 only reaches here
                out[(2*bp    )*NP + i    ] = (l0 - a0_sm[(2*bp    )*NP + i    ]) * INV_DT_SKIP;
                out[(2*bp + 1)*NP + i    ] = (h0 - a0_sm[(2*bp + 1)*NP + i    ]) * INV_DT_SKIP;
                out[(2*bp    )*NP + i + 1] = (l1 - a0_sm[(2*bp    )*NP + i + 1]) * INV_DT_SKIP;
                out[(2*bp + 1)*NP + i + 1] = (h1 - a0_sm[(2*bp + 1)*NP + i + 1]) * INV_DT_SKIP;
                continue; // falls out of loop at it==NITER-1
            }
        }

        // ---------- barrier 2: all CTAs read S; then zero own slice ----------
        __syncthreads();
        if (t == 0) {
            atom_inc_acqrel(&g_counter);
            const unsigned tgt2 = (unsigned)NCTA * (unsigned)(2*it + 2);
            while (ldacq(&g_counter) < tgt2) __nanosleep(32);
        }
        __syncthreads();
        if (t < 16) __stcg(&g_S[it & 1][cta*16 + t], 0.0f);
        // visibility of these zeros is ordered by this CTA's next acq_rel arrival
        __syncthreads();
    }
}

// ---------------- launcher ----------------
extern "C" void kernel_launch(void* const* d_in, const int* in_sizes, int n_in,
                              void* d_out, int out_size) {
    const float* state = (const float*)d_in[0];
    const float* Ap    = (const float*)d_in[1];
    const float* Wu    = (const float*)d_in[2];
    const float* Wv    = (const float*)d_in[3];
    const float* Pp    = (const float*)d_in[4];
    float* out = (float*)d_out;
    (void)in_sizes; (void)n_in; (void)out_size;

    cudaFuncSetAttribute(persist_kernel,
                         cudaFuncAttributeMaxDynamicSharedMemorySize, SMEM_TOTAL);

    init_kernel<<<1, 256>>>(Ap);
    persist_kernel<<<NCTA, NT, SMEM_TOTAL>>>(state, Wu, Wv, Pp, out);
}

// round 5
// speedup vs baseline: 1.1134x; 1.0450x over previous
#include <cuda_runtime.h>

#define NG      8000
#define NGATE   16000
#define NCTA    125
#define GPC     128      // gates per CTA: 125*128 = 16000
#define NB      32
#define NP      64
#define NITER   50
#define NT      512
#define DTF     0.02f
#define INV_DT_SKIP 2.5f

typedef unsigned long long u64;

// ---------------- device scratch ----------------
__device__ float    g_S[4][NB*NP];        // rotating reduction buffers
__device__ u64      g_invdup[2][NP*NP];   // inverses, j-major, value-duplicated
__device__ unsigned g_counter;

// ---------------- packed f32x2 + memory-order helpers ----------------
__device__ __forceinline__ u64 fma2(u64 a, u64 b, u64 c) {
    u64 d; asm("fma.rn.f32x2 %0, %1, %2, %3;" : "=l"(d) : "l"(a), "l"(b), "l"(c)); return d;
}
__device__ __forceinline__ u64 mul2(u64 a, u64 b) {
    u64 d; asm("mul.rn.f32x2 %0, %1, %2;" : "=l"(d) : "l"(a), "l"(b)); return d;
}
__device__ __forceinline__ u64 dup2(float x) {
    unsigned xi = __float_as_uint(x);
    u64 d; asm("mov.b64 %0, {%1, %2};" : "=l"(d) : "r"(xi), "r"(xi)); return d;
}
__device__ __forceinline__ void unpack2(u64 v, float& lo, float& hi) {
    unsigned a, b; asm("mov.b64 {%0, %1}, %2;" : "=r"(a), "=r"(b) : "l"(v));
    lo = __uint_as_float(a); hi = __uint_as_float(b);
}
__device__ __forceinline__ unsigned ldacq(const unsigned* p) {
    unsigned v; asm volatile("ld.acquire.gpu.u32 %0, [%1];" : "=r"(v) : "l"(p)); return v;
}
__device__ __forceinline__ unsigned atom_inc_acqrel(unsigned* p) {
    unsigned v, one = 1u;
    asm volatile("atom.add.acq_rel.gpu.u32 %0, [%1], %2;" : "=r"(v) : "l"(p), "r"(one)); return v;
}
__device__ __forceinline__ void redadd(float* p, float v) {
    asm volatile("red.add.f32 [%0], %1;" :: "l"(p), "f"(v));
}

// ---------------- init: matrix inverses (dup'd) + reset ----------------
__global__ void init_kernel(const float* __restrict__ Ap) {
    __shared__ float M[NP][2*NP + 1];
    __shared__ float fac[NP];
    __shared__ float s_piv;
    int t = threadIdx.x;

    for (int pass = 0; pass < 2; ++pass) {
        float dscale = (pass == 0) ? 1.0f : 3.0f;
        float ascale = (pass == 0) ? DTF : 2.0f * DTF;
        for (int idx = t; idx < NP*NP; idx += 256) {
            int i = idx >> 6, j = idx & 63;
            M[i][j]      = ((i == j) ? dscale : 0.0f) - ascale * Ap[idx];
            M[i][j + NP] = (i == j) ? 1.0f : 0.0f;
        }
        __syncthreads();
        for (int c = 0; c < NP; ++c) {
            if (t == 0) s_piv = 1.0f / M[c][c];
            __syncthreads();
            float ip = s_piv;
            if (t < 2*NP) M[c][t] *= ip;
            if (t < NP)   fac[t] = (t == c) ? 0.0f : M[t][c];
            __syncthreads();
            for (int idx = t; idx < NP * 2 * NP; idx += 256) {
                int r = idx >> 7, j = idx & 127;
                if (r != c) M[r][j] -= fac[r] * M[c][j];
            }
            __syncthreads();
        }
        // store j-major dup'd: invdup[pass][j*64 + i] = dup2(inv[i][j])
        for (int idx = t; idx < NP*NP; idx += 256) {
            int j = idx >> 6, i = idx & 63;
            g_invdup[pass][idx] = dup2(M[i][j + NP]);
        }
        __syncthreads();
    }
    for (int idx = t; idx < 4*NB*NP; idx += 256) ((float*)g_S)[idx] = 0.0f;
    if (t == 0) g_counter = 0u;
    __threadfence();
}

// ---------------- persistent kernel SMEM layout (bytes) ----------------
#define SM_W    0                 // [128 gl][64 k XOR-swz][4 comps] f32 : 131072
#define SM_PP   131072            // [128 g][64 p] f32                  : 32768
#define SM_F    163840            // [128 g] stride 144B, 16 u64 b-pairs: 18432
#define SM_A    182272            // [64 k][16 bp] u64 (a^T, b-paired)  : 8192
#define SM_R    190464            // [64 j][16 bp] u64                  : 8192
#define SM_INV  198656            // [64 j][64 i] u64 dup'd             : 32768
#define SMEM_TOTAL 231424

extern __shared__ char smem_raw[];

__global__ void __launch_bounds__(NT, 1)
persist_kernel(const float* __restrict__ state,
               const float* __restrict__ Wu, const float* __restrict__ Wv,
               const float* __restrict__ Pp, float* __restrict__ out)
{
    const int t   = threadIdx.x;
    const int cta = blockIdx.x;

    // ================= one-time staging =================
    // W slice: [gl][k^(gl&7)][comp] for conflict-free reads without padding
    for (int idx = t; idx < GPC*4*16; idx += NT) {
        int gl = idx >> 6, r = (idx >> 4) & 3, k4 = idx & 15;
        int gate = cta * GPC + gl;
        const float4* src = (const float4*)((gate < NG) ? Wu : Wv);
        int base = (gate < NG) ? gate : (gate - NG);
        float4 v = __ldg(src + (base + r*NG)*16 + k4);
        float vv[4] = {v.x, v.y, v.z, v.w};
        #pragma unroll
        for (int j = 0; j < 4; ++j) {
            int k = k4*4 + j;
            int kk = k ^ (gl & 7);
            *(float*)(smem_raw + SM_W + gl*1024 + kk*16 + r*4) = vv[j];
        }
    }
    // P_proj slice: [g][p]
    for (int idx = t; idx < (GPC*NP)/4; idx += NT) {
        int p = idx >> 5, g4 = idx & 31;
        float4 v = __ldg((const float4*)(Pp + p*NGATE + cta*GPC + g4*4));
        float vv[4] = {v.x, v.y, v.z, v.w};
        #pragma unroll
        for (int j = 0; j < 4; ++j)
            *(float*)(smem_raw + SM_PP + (g4*4 + j)*256 + p*4) = vv[j];
    }
    // a^T (k-major, batch-paired)
    for (int idx = t; idx < NB*NP; idx += NT) {
        int b = idx >> 6, k = idx & 63;
        ((float*)(smem_raw + SM_A + k*128 + (b >> 1)*8))[b & 1] = state[idx];
    }
    // inv1 dup'd
    for (int m = t; m < NP*NP; m += NT)
        ((u64*)(smem_raw + SM_INV))[m] = g_invdup[0][m];

    // static mappings
    const int gl = t >> 2, q = t & 3;                  // phase 1
    const char* wp = smem_raw + SM_W + gl*1024;
    const unsigned xorb = (unsigned)(gl & 7) * 16u;
    const int b2 = t >> 4, pq = t & 15;                // phase 2: (batch, p-quad)
    const int bp = t & 15, i2 = t >> 4;                // matvec:  (b-pair, i-pair)

    float aprv[4] = {0, 0, 0, 0}, fprv[4] = {0, 0, 0, 0};

    __syncthreads();

    for (int it = 0; it < NITER; ++it) {
        // ========== phase 1: z = a @ W^T (4 comps), f = u*dx + v*dy ==========
        u64 ac0[4], ac1[4], ac2[4], ac3[4];
        #pragma unroll
        for (int i = 0; i < 4; ++i) { ac0[i]=0; ac1[i]=0; ac2[i]=0; ac3[i]=0; }

        #pragma unroll 4
        for (int k = 0; k < NP; ++k) {
            float4 w4 = *(const float4*)(wp + (((unsigned)(k*16)) ^ xorb));
            ulonglong2 a01 = *(const ulonglong2*)(smem_raw + SM_A + k*128 + q*32);
            ulonglong2 a23 = *(const ulonglong2*)(smem_raw + SM_A + k*128 + q*32 + 16);
            u64 d0 = dup2(w4.x), d1 = dup2(w4.y), d2 = dup2(w4.z), d3 = dup2(w4.w);
            u64 av0 = a01.x, av1 = a01.y, av2 = a23.x, av3 = a23.y;
            ac0[0]=fma2(d0,av0,ac0[0]); ac0[1]=fma2(d0,av1,ac0[1]);
            ac0[2]=fma2(d0,av2,ac0[2]); ac0[3]=fma2(d0,av3,ac0[3]);
            ac1[0]=fma2(d1,av0,ac1[0]); ac1[1]=fma2(d1,av1,ac1[1]);
            ac1[2]=fma2(d1,av2,ac1[2]); ac1[3]=fma2(d1,av3,ac1[3]);
            ac2[0]=fma2(d2,av0,ac2[0]); ac2[1]=fma2(d2,av1,ac2[1]);
            ac2[2]=fma2(d2,av2,ac2[2]); ac2[3]=fma2(d2,av3,ac2[3]);
            ac3[0]=fma2(d3,av0,ac3[0]); ac3[1]=fma2(d3,av1,ac3[1]);
            ac3[2]=fma2(d3,av2,ac3[2]); ac3[3]=fma2(d3,av3,ac3[3]);
        }
        {
            u64 f0 = fma2(ac1[0], ac3[0], mul2(ac0[0], ac2[0]));
            u64 f1 = fma2(ac1[1], ac3[1], mul2(ac0[1], ac2[1]));
            u64 f2 = fma2(ac1[2], ac3[2], mul2(ac0[2], ac2[2]));
            u64 f3 = fma2(ac1[3], ac3[3], mul2(ac0[3], ac2[3]));
            char* fb = smem_raw + SM_F + gl*144 + q*32;
            *(ulonglong2*)(fb)      = make_ulonglong2(f0, f1);
            *(ulonglong2*)(fb + 16) = make_ulonglong2(f2, f3);
        }
        __syncthreads();

        // ========== phase 2: S[b][p] += sum_g f[b][g] * Pp[p][g] ==========
        {
            float* Sb = g_S[it & 3];
            u64 acc0 = 0, acc1 = 0;
            const char* fbase  = smem_raw + SM_F + (b2 >> 1)*8 + (b2 & 1)*4;
            const char* ppbase = smem_raw + SM_PP + pq*16;
            #pragma unroll 4
            for (int g = 0; g < GPC; ++g) {
                float fs = *(const float*)(fbase + g*144);
                u64 fd = dup2(fs);
                ulonglong2 pv = *(const ulonglong2*)(ppbase + g*256);
                acc0 = fma2(fd, pv.x, acc0);
                acc1 = fma2(fd, pv.y, acc1);
            }
            float l0, h0, l1, h1;
            unpack2(acc0, l0, h0); unpack2(acc1, l1, h1);
            redadd(Sb + b2*NP + pq*4    , l0);
            redadd(Sb + b2*NP + pq*4 + 1, h0);
            redadd(Sb + b2*NP + pq*4 + 2, l1);
            redadd(Sb + b2*NP + pq*4 + 3, h1);
        }

        // ========== single global barrier ==========
        __threadfence();
        __syncthreads();
        if (t == 0) atom_inc_acqrel(&g_counter);
        if (it == NITER - 1 && cta != 0) return;      // uniform exit; CTA0 finishes
        if (t == 0) {
            const unsigned tgt = (unsigned)NCTA * (unsigned)(it + 1);
            while (ldacq(&g_counter) < tgt) { }
        }
        __syncthreads();

        // zero the buffer used 1 iteration ago (rewritten at it+3; safe per R=4 chain)
        if (t < 17) {
            int z = cta*17 + t;
            if (z < NB*NP) __stcg(&g_S[(it + 3) & 3][z], 0.0f);
        }

        // ========== update (redundant per CTA, all in SMEM/regs) ==========
        {
            const float* Sb = g_S[it & 3];
            #pragma unroll
            for (int e = 0; e < 4; ++e) {
                int idx = t + e*NT;
                int bb_ = idx >> 6, j = idx & 63;
                float f  = -__ldcv(Sb + idx);
                float av = ((const float*)(smem_raw + SM_A + j*128 + (bb_ >> 1)*8))[bb_ & 1];
                float r;
                if (it == 0) r = av + DTF * f;
                else         r = 4.0f*av - aprv[e] + 4.0f*DTF*f - 2.0f*DTF*fprv[e];
                aprv[e] = av; fprv[e] = f;
                ((float*)(smem_raw + SM_R + j*128 + (bb_ >> 1)*8))[bb_ & 1] = r;
            }
        }
        __syncthreads();
        {
            // a_next = inv @ r
            u64 m0 = 0, m1 = 0;
            #pragma unroll 4
            for (int j = 0; j < NP; ++j) {
                u64 rv = *(const u64*)(smem_raw + SM_R + j*128 + bp*8);
                ulonglong2 iv = *(const ulonglong2*)(smem_raw + SM_INV + j*512 + i2*16);
                m0 = fma2(rv, iv.x, m0);
                m1 = fma2(rv, iv.y, m1);
            }
            int i = i2*2;
            if (it < NITER - 1) {
                *(u64*)(smem_raw + SM_A + (i    )*128 + bp*8) = m0;
                *(u64*)(smem_raw + SM_A + (i + 1)*128 + bp*8) = m1;
            } else {
                float l0, h0, l1, h1;
                unpack2(m0, l0, h0); unpack2(m1, l1, h1);
                out[(2*bp    )*NP + i    ] = (l0 - __ldg(&state[(2*bp    )*NP + i    ])) * INV_DT_SKIP;
                out[(2*bp + 1)*NP + i    ] = (h0 - __ldg(&state[(2*bp + 1)*NP + i    ])) * INV_DT_SKIP;
                out[(2*bp    )*NP + i + 1] = (l1 - __ldg(&state[(2*bp    )*NP + i + 1])) * INV_DT_SKIP;
                out[(2*bp + 1)*NP + i + 1] = (h1 - __ldg(&state[(2*bp + 1)*NP + i + 1])) * INV_DT_SKIP;
            }
        }
        if (it == 0) {  // switch to inv2 for all remaining iterations
            __syncthreads();
            for (int m = t; m < NP*NP; m += NT)
                ((u64*)(smem_raw + SM_INV))[m] = g_invdup[1][m];
        }
        __syncthreads();
    }
}

// ---------------- launcher ----------------
extern "C" void kernel_launch(void* const* d_in, const int* in_sizes, int n_in,
                              void* d_out, int out_size) {
    const float* state = (const float*)d_in[0];
    const float* Ap    = (const float*)d_in[1];
    const float* Wu    = (const float*)d_in[2];
    const float* Wv    = (const float*)d_in[3];
    const float* Pp    = (const float*)d_in[4];
    float* out = (float*)d_out;
    (void)in_sizes; (void)n_in; (void)out_size;

    cudaFuncSetAttribute(persist_kernel,
                         cudaFuncAttributeMaxDynamicSharedMemorySize, SMEM_TOTAL);

    init_kernel<<<1, 256>>>(Ap);
    persist_kernel<<<NCTA, NT, SMEM_TOTAL>>>(state, Wu, Wv, Pp, out);
}